// round 11
// baseline (speedup 1.0000x reference)
#include <cuda_runtime.h>
#include <cuda_bf16.h>
#include <math.h>
#include <cstdint>

// Problem constants (GCNAggregator): B=4096, K=32, U=32768, V=100000, D=128
#define GCN_B 4096
#define GCN_K 32
#define GCN_U 32768
#define GCN_D 128

#define ROWS_PER_BLK 4                      // 4 rows x 2 warps = 8 warps/block
#define AGG_THREADS (ROWS_PER_BLK * 64)

// Scratch (no cudaMalloc allowed)
__device__ int g_col_deg[GCN_U];

// ---------------------------------------------------------------------------
// Kernel 1: per-row dedupe (one warp per row) + column degree accumulation.
// match_any: one instruction instead of a 32-step shfl chain.
// ---------------------------------------------------------------------------
__global__ void dedupe_degree_kernel(const int* __restrict__ neigh_cols) {
    int warp_in_block = threadIdx.x >> 5;
    int lane = threadIdx.x & 31;
    int b = blockIdx.x * (blockDim.x >> 5) + warp_in_block;

    int c = neigh_cols[b * GCN_K + lane];
    unsigned peers = __match_any_sync(0xFFFFFFFFu, c);
    bool first = ((int)__ffs(peers) - 1) == lane;   // lowest lane holding c

    if (first) atomicAdd(&g_col_deg[c], 1);         // spread addresses -> cheap
}

// ---------------------------------------------------------------------------
// Kernel 2: aggregation, split-K x2 + decoupled weight chain.
// Two warps per row; warp h gathers neighbors [16h, 16h+16) with a depth-8
// rolling __ldcg pipeline. Each warp computes the full-row dedupe locally
// (match_any) and writes only its warp-private half of the smem (off, w)
// table -> no block sync in the mainloop; one __syncthreads before the
// cross-warp partial combine. Duplicates carry w=0 -> branch-free.
// ---------------------------------------------------------------------------
__global__ void __launch_bounds__(AGG_THREADS)
aggregate_kernel(const int* __restrict__ neigh_cols,
                 const int* __restrict__ unique_ids,
                 const float4* __restrict__ embed_table4,  // [V, 32] float4
                 float4* __restrict__ out4) {              // [B, 32] float4
    const int warp = threadIdx.x >> 5;
    const int lane = threadIdx.x & 31;
    const int r    = warp >> 1;              // row slot in block
    const int h    = warp & 1;               // half: neighbors [16h, 16h+16)
    const int b    = blockIdx.x * ROWS_PER_BLK + r;

    __shared__ int    s_off[ROWS_PER_BLK][GCN_K];
    __shared__ float  s_w[ROWS_PER_BLK][GCN_K];
    __shared__ float4 s_part[ROWS_PER_BLK][32];

    // ---- step 1: offsets first (shortest chain); publish own half only ----
    const int c = neigh_cols[b * GCN_K + lane];
    const int off4 = __ldg(&unique_ids[c]) * (GCN_D / 4);
    const bool mine = (lane >> 4) == h;
    if (mine) s_off[r][lane] = off4;
    __syncwarp();

    // ---- step 2: launch this warp's gather pipeline immediately ----
    constexpr int P = 8;
    const int kbase = h * 16;
    float4 buf[P];
    #pragma unroll
    for (int i = 0; i < P; i++)
        buf[i] = __ldcg(&embed_table4[s_off[r][kbase + i] + lane]);

    // ---- step 3: weight chain resolves under the in-flight gathers ----
    unsigned peers = __match_any_sync(0xFFFFFFFFu, c);
    bool first = ((int)__ffs(peers) - 1) == lane;
    unsigned mask = __ballot_sync(0xFFFFFFFFu, first);
    float w = 0.0f;
    if (first) {
        int deg = __ldcg(&g_col_deg[c]);            // >= 1 for first occurrences
        w = rsqrtf((float)deg);
    }
    w *= rsqrtf((float)__popc(mask));               // fold row scale into lane weight
    if (mine) s_w[r][lane] = w;
    __syncwarp();

    // ---- step 4: rolling FMA + refill over this warp's 16 neighbors ----
    float4 acc = make_float4(0.f, 0.f, 0.f, 0.f);
    #pragma unroll
    for (int k = 0; k < 16; k++) {
        float4 v  = buf[k & (P - 1)];
        float  wk = s_w[r][kbase + k];
        acc.x = fmaf(wk, v.x, acc.x);
        acc.y = fmaf(wk, v.y, acc.y);
        acc.z = fmaf(wk, v.z, acc.z);
        acc.w = fmaf(wk, v.w, acc.w);
        if (k + P < 16)
            buf[k & (P - 1)] = __ldcg(&embed_table4[s_off[r][kbase + k + P] + lane]);
    }

    // ---- step 5: cross-warp combine; half 0 stores ----
    if (h == 1) s_part[r][lane] = acc;
    __syncthreads();
    if (h == 0) {
        float4 p = s_part[r][lane];
        acc.x += p.x; acc.y += p.y; acc.z += p.z; acc.w += p.w;
        out4[b * (GCN_D / 4) + lane] = acc;
    }
}

// ---------------------------------------------------------------------------
extern "C" void kernel_launch(void* const* d_in, const int* in_sizes, int n_in,
                              void* d_out, int out_size) {
    const int*    neigh_cols   = (const int*)d_in[0];
    const int*    unique_ids   = (const int*)d_in[1];
    const float4* embed_table4 = (const float4*)d_in[2];
    float4*       out4         = (float4*)d_out;

    // Zero column degrees via a graph memset node (no dedicated kernel launch).
    void* col_deg_ptr = nullptr;
    cudaGetSymbolAddress(&col_deg_ptr, g_col_deg);
    cudaMemsetAsync(col_deg_ptr, 0, GCN_U * sizeof(int));

    dedupe_degree_kernel<<<GCN_B / 8, 256>>>(neigh_cols);
    aggregate_kernel<<<GCN_B / ROWS_PER_BLK, AGG_THREADS>>>(
        neigh_cols, unique_ids, embed_table4, out4);
}